// round 14
// baseline (speedup 1.0000x reference)
#include <cuda_runtime.h>
#include <cuda_bf16.h>
#include <math.h>
#include <cstdint>

#define MAXN 100000
#define MAXE 1200000
#define D    64
#define HID  128
#define C    40
#define CAP  128

// ---------------- device scratch ----------------
__device__ int      d_deg[MAXN];
__device__ int      d_colb[(size_t)MAXN * CAP];
__device__ __align__(16) uint32_t d_a1h[(size_t)MAXN * D];   // agg1 tf32 hi
__device__ __align__(16) uint32_t d_a1l[(size_t)MAXN * D];   // agg1 tf32 lo
__device__ __align__(16) uint32_t d_w1h[D * HID];
__device__ __align__(16) uint32_t d_w1l[D * HID];
__device__ __align__(16) uint32_t d_w2h[HID * C];
__device__ __align__(16) uint32_t d_w2l[HID * C];
__device__ __align__(16) float d_y[(size_t)MAXN * C];

// ---------------- tf32 helpers ----------------
__device__ __forceinline__ uint32_t f2tf32(float x) {
    uint32_t r;
    asm("cvt.rna.tf32.f32 %0, %1;" : "=r"(r) : "f"(x));
    return r;
}
#define MMA_TF32(cc, a0, a1, a2, a3, b0, b1) \
    asm volatile("mma.sync.aligned.m16n8k8.row.col.f32.tf32.tf32.f32 " \
        "{%0,%1,%2,%3}, {%4,%5,%6,%7}, {%8,%9}, {%0,%1,%2,%3};" \
        : "+f"((cc)[0]), "+f"((cc)[1]), "+f"((cc)[2]), "+f"((cc)[3]) \
        : "r"(a0), "r"(a1), "r"(a2), "r"(a3), "r"(b0), "r"(b1))

// ---------------- build ----------------
__global__ void k_init(int n) {
    int i = blockIdx.x * blockDim.x + threadIdx.x;
    if (i < n) d_deg[i] = 0;
}

__global__ void k_build(const int2* __restrict__ adj, int e) {
    int i = blockIdx.x * blockDim.x + threadIdx.x;
    if (i < e) {
        int2 ed = adj[i];
        int p = atomicAdd(&d_deg[ed.y], 1);
        d_colb[ed.y * CAP + p] = ed.x;
    }
}

// ---------------- one-shot weight split ----------------
__global__ void k_wsplit(const float* __restrict__ W1, const float* __restrict__ W2) {
    int i = blockIdx.x * blockDim.x + threadIdx.x;
    if (i < D * HID) {
        float v = W1[i];
        uint32_t hi = f2tf32(v);
        d_w1h[i] = hi;
        d_w1l[i] = f2tf32(v - __uint_as_float(hi));
    }
    if (i < HID * C) {
        float v = W2[i];
        uint32_t hi = f2tf32(v);
        d_w2h[i] = hi;
        d_w2l[i] = f2tf32(v - __uint_as_float(hi));
    }
}

// ---------------- layer-1 gather, writes pre-split tf32 hi/lo ----------------
__global__ void k_agg1(const float* __restrict__ h, int n) {
    int w = (blockIdx.x * blockDim.x + threadIdx.x) >> 5;
    int lane = threadIdx.x & 31;
    if (w >= n) return;
    int half = lane >> 4;
    int q = lane & 15;
    const float4* h4 = (const float4*)h;

    float4 acc = make_float4(0.f, 0.f, 0.f, 0.f);
    if (half == 0) acc = h4[w * 16 + q];          // self-loop
    const int* col = d_colb + w * CAP;
    int end = d_deg[w];
    int j = 0;
    for (; j + 7 < end; j += 8) {
        int s0 = col[j + half];
        int s1 = col[j + 2 + half];
        int s2 = col[j + 4 + half];
        int s3 = col[j + 6 + half];
        float4 v0 = h4[s0 * 16 + q];
        float4 v1 = h4[s1 * 16 + q];
        float4 v2 = h4[s2 * 16 + q];
        float4 v3 = h4[s3 * 16 + q];
        acc.x += (v0.x + v1.x) + (v2.x + v3.x);
        acc.y += (v0.y + v1.y) + (v2.y + v3.y);
        acc.z += (v0.z + v1.z) + (v2.z + v3.z);
        acc.w += (v0.w + v1.w) + (v2.w + v3.w);
    }
    if (j + 3 < end) {
        int s0 = col[j + half];
        int s1 = col[j + 2 + half];
        float4 v0 = h4[s0 * 16 + q];
        float4 v1 = h4[s1 * 16 + q];
        acc.x += v0.x + v1.x;
        acc.y += v0.y + v1.y;
        acc.z += v0.z + v1.z;
        acc.w += v0.w + v1.w;
        j += 4;
    }
    if (j + 1 < end) {
        int s = col[j + half];
        float4 v = h4[s * 16 + q];
        acc.x += v.x; acc.y += v.y; acc.z += v.z; acc.w += v.w;
        j += 2;
    }
    if (j < end && half == 0) {
        int s = col[j];
        float4 v = h4[s * 16 + q];
        acc.x += v.x; acc.y += v.y; acc.z += v.z; acc.w += v.w;
    }
    acc.x += __shfl_xor_sync(0xffffffffu, acc.x, 16);
    acc.y += __shfl_xor_sync(0xffffffffu, acc.y, 16);
    acc.z += __shfl_xor_sync(0xffffffffu, acc.z, 16);
    acc.w += __shfl_xor_sync(0xffffffffu, acc.w, 16);
    if (half == 0) {
        uint4 hv, lv;
        hv.x = f2tf32(acc.x); lv.x = f2tf32(acc.x - __uint_as_float(hv.x));
        hv.y = f2tf32(acc.y); lv.y = f2tf32(acc.y - __uint_as_float(hv.y));
        hv.z = f2tf32(acc.z); lv.z = f2tf32(acc.z - __uint_as_float(hv.z));
        hv.w = f2tf32(acc.w); lv.w = f2tf32(acc.w - __uint_as_float(hv.w));
        ((uint4*)d_a1h)[w * 16 + q] = hv;
        ((uint4*)d_a1l)[w * 16 + q] = lv;
    }
}

// ---------------- TF32 mma: GEMM1 + ReLU + GEMM2 (64 nodes/block) ----------------
// smem layout (word offsets):
// phase 1: SA_HI 0 [64x68] | SA_LO 4352 [64x68] | W1_HI 8704 [64x136] | W1_LO 17408 [64x136]
// phase 2: X_HI 0 [64x132] | X_LO 8448 [64x132] | W2_HI 16896 [128x40] | W2_LO 22016 [128x40]
#define WO_SA_HI 0
#define WO_SA_LO 4352
#define WO_W1_HI 8704
#define WO_W1_LO 17408
#define WO_X_HI  0
#define WO_X_LO  8448
#define WO_W2_HI 16896
#define WO_W2_LO 22016
#define SM_WORDS 27136
#define SM_BYTES (SM_WORDS * 4)   // 108544

__global__ void __launch_bounds__(256, 2) k_gemm(const float* __restrict__ b1, int n) {
    extern __shared__ uint32_t smw[];
    int tid = threadIdx.x;
    int w = tid >> 5, lane = tid & 31;
    int g = lane >> 2, tg = lane & 3;
    int node0 = blockIdx.x * 64;

    // ---- copy pre-split W1 -> smem [k][136] (uint4) ----
    {
        uint32_t* WH = smw + WO_W1_HI;
        uint32_t* WL = smw + WO_W1_LO;
        const uint4* GH = (const uint4*)d_w1h;
        const uint4* GL = (const uint4*)d_w1l;
#pragma unroll
        for (int i = 0; i < 8; i++) {
            int i4 = tid + i * 256;        // 2048 uint4 total
            int k = i4 >> 5, n4 = i4 & 31;
            *(uint4*)&WH[k * 136 + n4 * 4] = GH[i4];
            *(uint4*)&WL[k * 136 + n4 * 4] = GL[i4];
        }
    }
    // ---- copy pre-split A tile -> smem [node][68] (uint4) ----
    {
        uint32_t* AH = smw + WO_SA_HI;
        uint32_t* AL = smw + WO_SA_LO;
        const uint4* GH = (const uint4*)d_a1h + node0 * 16;
        const uint4* GL = (const uint4*)d_a1l + node0 * 16;
        int lim4 = (n - node0) * 16;       // uint4 count in range
#pragma unroll
        for (int i = 0; i < 4; i++) {
            int i4 = tid + i * 256;        // 1024 uint4 total
            int nodeL = i4 >> 4, k4 = i4 & 15;
            uint4 hv = make_uint4(0, 0, 0, 0), lv = make_uint4(0, 0, 0, 0);
            if (i4 < lim4) { hv = GH[i4]; lv = GL[i4]; }
            *(uint4*)&AH[nodeL * 68 + k4 * 4] = hv;
            *(uint4*)&AL[nodeL * 68 + k4 * 4] = lv;
        }
    }
    __syncthreads();

    // ---- phase 1: x1 = relu(A @ W1 + b1) via tf32 mma (2-split, 3 products) ----
    float c1[8][4];
    {
        const uint32_t* AH = smw + WO_SA_HI;
        const uint32_t* AL = smw + WO_SA_LO;
        const uint32_t* WH = smw + WO_W1_HI;
        const uint32_t* WL = smw + WO_W1_LO;
        int mt = w & 3;
        int nhalf = w >> 2;
#pragma unroll
        for (int nt = 0; nt < 8; nt++)
#pragma unroll
            for (int i = 0; i < 4; i++) c1[nt][i] = 0.f;

#pragma unroll
        for (int kt = 0; kt < 8; kt++) {
            int ar = (mt * 16 + g) * 68 + kt * 8 + tg;
            uint32_t ah0 = AH[ar],     ah1 = AH[ar + 8 * 68];
            uint32_t ah2 = AH[ar + 4], ah3 = AH[ar + 8 * 68 + 4];
            uint32_t al0 = AL[ar],     al1 = AL[ar + 8 * 68];
            uint32_t al2 = AL[ar + 4], al3 = AL[ar + 8 * 68 + 4];
#pragma unroll
            for (int nt = 0; nt < 8; nt++) {
                int br = (kt * 8 + tg) * 136 + nhalf * 64 + nt * 8 + g;
                uint32_t bh0 = WH[br], bh1 = WH[br + 4 * 136];
                uint32_t bl0 = WL[br], bl1 = WL[br + 4 * 136];
                MMA_TF32(c1[nt], ah0, ah1, ah2, ah3, bh0, bh1);
                MMA_TF32(c1[nt], ah0, ah1, ah2, ah3, bl0, bl1);
                MMA_TF32(c1[nt], al0, al1, al2, al3, bh0, bh1);
            }
        }
    }
    __syncthreads();   // SA/W1 reads done -> overlay X

    // ---- write x1 (bias+relu) as tf32 splits into X_HI/X_LO [node][132] ----
    {
        uint32_t* XH = smw + WO_X_HI;
        uint32_t* XL = smw + WO_X_LO;
        int mt = w & 3;
        int nhalf = w >> 2;
#pragma unroll
        for (int nt = 0; nt < 8; nt++) {
            int col = nhalf * 64 + nt * 8 + tg * 2;
            float2 bb = *(const float2*)&b1[col];
#pragma unroll
            for (int ip = 0; ip < 2; ip++) {
                int row = mt * 16 + g + ip * 8;
                float v0 = fmaxf(c1[nt][ip * 2 + 0] + bb.x, 0.f);
                float v1 = fmaxf(c1[nt][ip * 2 + 1] + bb.y, 0.f);
                uint32_t h0 = f2tf32(v0), h1 = f2tf32(v1);
                uint32_t l0 = f2tf32(v0 - __uint_as_float(h0));
                uint32_t l1 = f2tf32(v1 - __uint_as_float(h1));
                *(uint2*)&XH[row * 132 + col] = make_uint2(h0, h1);
                *(uint2*)&XL[row * 132 + col] = make_uint2(l0, l1);
            }
        }
    }
    // ---- copy pre-split W2 (linear [k*40+n], 1280 uint4) ----
    {
        uint32_t* WH = smw + WO_W2_HI;
        uint32_t* WL = smw + WO_W2_LO;
        const uint4* GH = (const uint4*)d_w2h;
        const uint4* GL = (const uint4*)d_w2l;
#pragma unroll
        for (int i = 0; i < 5; i++) {
            int i4 = tid + i * 256;
            ((uint4*)WH)[i4] = GH[i4];
            ((uint4*)WL)[i4] = GL[i4];
        }
    }
    __syncthreads();

    // ---- phase 2: y = x1 @ W2 via tf32 mma; 2-way k-split ----
    float c2[5][4];
    {
        const uint32_t* XH = smw + WO_X_HI;
        const uint32_t* XL = smw + WO_X_LO;
        const uint32_t* WH = smw + WO_W2_HI;
        const uint32_t* WL = smw + WO_W2_LO;
        int mt = w & 3;
        int kh = w >> 2;
#pragma unroll
        for (int nt = 0; nt < 5; nt++)
#pragma unroll
            for (int i = 0; i < 4; i++) c2[nt][i] = 0.f;

#pragma unroll
        for (int kt = 0; kt < 8; kt++) {
            int k0 = kh * 64 + kt * 8;
            int ar = (mt * 16 + g) * 132 + k0 + tg;
            uint32_t ah0 = XH[ar],     ah1 = XH[ar + 8 * 132];
            uint32_t ah2 = XH[ar + 4], ah3 = XH[ar + 8 * 132 + 4];
            uint32_t al0 = XL[ar],     al1 = XL[ar + 8 * 132];
            uint32_t al2 = XL[ar + 4], al3 = XL[ar + 8 * 132 + 4];
#pragma unroll
            for (int nt = 0; nt < 5; nt++) {
                int br = (k0 + tg) * 40 + nt * 8 + g;
                uint32_t bh0 = WH[br], bh1 = WH[br + 4 * 40];
                uint32_t bl0 = WL[br], bl1 = WL[br + 4 * 40];
                MMA_TF32(c2[nt], ah0, ah1, ah2, ah3, bh0, bh1);
                MMA_TF32(c2[nt], ah0, ah1, ah2, ah3, bl0, bl1);
                MMA_TF32(c2[nt], al0, al1, al2, al3, bh0, bh1);
            }
        }
    }
    __syncthreads();

    // ---- reduce k-halves and write y ----
    {
        float* SC = (float*)(smw + WO_X_HI);   // [64][44] scratch
        int mt = w & 3;
        int kh = w >> 2;
        if (kh == 1) {
#pragma unroll
            for (int nt = 0; nt < 5; nt++)
#pragma unroll
                for (int ip = 0; ip < 2; ip++) {
                    int row = mt * 16 + g + ip * 8;
                    int col = nt * 8 + tg * 2;
                    *(float2*)&SC[row * 44 + col] =
                        make_float2(c2[nt][ip * 2], c2[nt][ip * 2 + 1]);
                }
        }
        __syncthreads();
        if (kh == 0) {
#pragma unroll
            for (int nt = 0; nt < 5; nt++)
#pragma unroll
                for (int ip = 0; ip < 2; ip++) {
                    int row = mt * 16 + g + ip * 8;
                    int gn = node0 + row;
                    int col = nt * 8 + tg * 2;
                    float2 o = *(float2*)&SC[row * 44 + col];
                    o.x += c2[nt][ip * 2];
                    o.y += c2[nt][ip * 2 + 1];
                    if (gn < n) *(float2*)&d_y[gn * C + col] = o;
                }
        }
    }
}

// ---------------- layer-2 aggregation + bias + softmax ----------------
__global__ void k_agg2_softmax(const float* __restrict__ b2, float* __restrict__ out, int n) {
    int w = (blockIdx.x * blockDim.x + threadIdx.x) >> 5;
    int lane = threadIdx.x & 31;
    if (w >= n) return;

    int g = lane / 10;
    int q = lane - g * 10;
    bool act = (lane < 30);
    const float4* Y4 = (const float4*)d_y;

    float4 acc = make_float4(0.f, 0.f, 0.f, 0.f);
    if (act && g == 0) acc = Y4[w * 10 + q];

    const int* col = d_colb + w * CAP;
    int end = d_deg[w];
    int j = 0;
    for (; j + 11 < end; j += 12) {
        if (act) {
            int s0 = col[j + g];
            int s1 = col[j + 3 + g];
            int s2 = col[j + 6 + g];
            int s3 = col[j + 9 + g];
            float4 v0 = Y4[s0 * 10 + q];
            float4 v1 = Y4[s1 * 10 + q];
            float4 v2 = Y4[s2 * 10 + q];
            float4 v3 = Y4[s3 * 10 + q];
            acc.x += (v0.x + v1.x) + (v2.x + v3.x);
            acc.y += (v0.y + v1.y) + (v2.y + v3.y);
            acc.z += (v0.z + v1.z) + (v2.z + v3.z);
            acc.w += (v0.w + v1.w) + (v2.w + v3.w);
        }
    }
    if (j + 5 < end) {
        if (act) {
            int s0 = col[j + g];
            int s1 = col[j + 3 + g];
            float4 v0 = Y4[s0 * 10 + q];
            float4 v1 = Y4[s1 * 10 + q];
            acc.x += v0.x + v1.x;
            acc.y += v0.y + v1.y;
            acc.z += v0.z + v1.z;
            acc.w += v0.w + v1.w;
        }
        j += 6;
    }
    if (j + 2 < end) {
        if (act) {
            int s = col[j + g];
            float4 v = Y4[s * 10 + q];
            acc.x += v.x; acc.y += v.y; acc.z += v.z; acc.w += v.w;
        }
        j += 3;
    }
    int rem = end - j;
    if (act && g < rem) {
        int s = col[j + g];
        float4 v = Y4[s * 10 + q];
        acc.x += v.x; acc.y += v.y; acc.z += v.z; acc.w += v.w;
    }

    acc.x += __shfl_sync(0xffffffffu, acc.x, lane + 10) + __shfl_sync(0xffffffffu, acc.x, lane + 20);
    acc.y += __shfl_sync(0xffffffffu, acc.y, lane + 10) + __shfl_sync(0xffffffffu, acc.y, lane + 20);
    acc.z += __shfl_sync(0xffffffffu, acc.z, lane + 10) + __shfl_sync(0xffffffffu, acc.z, lane + 20);
    acc.w += __shfl_sync(0xffffffffu, acc.w, lane + 10) + __shfl_sync(0xffffffffu, acc.w, lane + 20);

    bool own = (lane < 10);
    if (own) {
        acc.x += b2[lane * 4 + 0];
        acc.y += b2[lane * 4 + 1];
        acc.z += b2[lane * 4 + 2];
        acc.w += b2[lane * 4 + 3];
    }
    float m = own ? fmaxf(fmaxf(acc.x, acc.y), fmaxf(acc.z, acc.w)) : -1e30f;
#pragma unroll
    for (int off = 16; off; off >>= 1)
        m = fmaxf(m, __shfl_xor_sync(0xffffffffu, m, off));
    float e0 = __expf(acc.x - m);
    float e1 = __expf(acc.y - m);
    float e2 = __expf(acc.z - m);
    float e3 = __expf(acc.w - m);
    float s = own ? (e0 + e1) + (e2 + e3) : 0.f;
#pragma unroll
    for (int off = 16; off; off >>= 1)
        s += __shfl_xor_sync(0xffffffffu, s, off);
    float inv = 1.f / s;
    if (own) {
        float* o = out + w * C + lane * 4;
        o[0] = e0 * inv;
        o[1] = e1 * inv;
        o[2] = e2 * inv;
        o[3] = e3 * inv;
    }
}

// ---------------- launch ----------------
extern "C" void kernel_launch(void* const* d_in, const int* in_sizes, int n_in,
                              void* d_out, int out_size) {
    const float* h   = (const float*)d_in[0];
    const int*   adj = (const int*)d_in[1];
    const float* W1  = (const float*)d_in[2];
    const float* b1  = (const float*)d_in[3];
    const float* W2  = (const float*)d_in[4];
    const float* b2  = (const float*)d_in[5];
    float* out = (float*)d_out;

    int n = in_sizes[0] / D;
    int e = in_sizes[1] / 2;
    if (n > MAXN) n = MAXN;
    if (e > MAXE) e = MAXE;

    cudaFuncSetAttribute(k_gemm, cudaFuncAttributeMaxDynamicSharedMemorySize, SM_BYTES);

    k_init<<<(n + 255) / 256, 256>>>(n);
    k_build<<<(e + 255) / 256, 256>>>((const int2*)adj, e);
    k_wsplit<<<(D * HID + 255) / 256, 256>>>(W1, W2);

    k_agg1<<<(n * 32 + 255) / 256, 256>>>(h, n);
    k_gemm<<<(n + 63) / 64, 256, SM_BYTES>>>(b1, n);
    k_agg2_softmax<<<(n * 32 + 255) / 256, 256>>>(b2, out, n);
}

// round 15
// speedup vs baseline: 1.0513x; 1.0513x over previous
#include <cuda_runtime.h>
#include <cuda_bf16.h>
#include <math.h>
#include <cstdint>

#define MAXN 100000
#define MAXE 1200000
#define D    64
#define HID  128
#define C    40
#define CAP  128

// ---------------- device scratch ----------------
__device__ int      d_deg[MAXN];
__device__ int      d_colb[(size_t)MAXN * CAP];
__device__ __align__(16) float d_agg1[(size_t)MAXN * D];   // 25.6 MB (fp32, single copy)
__device__ __align__(16) uint32_t d_w1h[D * HID];
__device__ __align__(16) uint32_t d_w1l[D * HID];
__device__ __align__(16) uint32_t d_w2h[HID * C];
__device__ __align__(16) uint32_t d_w2l[HID * C];
__device__ __align__(16) float d_y[(size_t)MAXN * C];

// ---------------- tf32 helpers ----------------
__device__ __forceinline__ uint32_t f2tf32(float x) {
    uint32_t r;
    asm("cvt.rna.tf32.f32 %0, %1;" : "=r"(r) : "f"(x));
    return r;
}
#define MMA_TF32(cc, a0, a1, a2, a3, b0, b1) \
    asm volatile("mma.sync.aligned.m16n8k8.row.col.f32.tf32.tf32.f32 " \
        "{%0,%1,%2,%3}, {%4,%5,%6,%7}, {%8,%9}, {%0,%1,%2,%3};" \
        : "+f"((cc)[0]), "+f"((cc)[1]), "+f"((cc)[2]), "+f"((cc)[3]) \
        : "r"(a0), "r"(a1), "r"(a2), "r"(a3), "r"(b0), "r"(b1))

// ---------------- build ----------------
__global__ void k_init(int n) {
    int i = blockIdx.x * blockDim.x + threadIdx.x;
    if (i < n) d_deg[i] = 0;
}

__global__ void k_build(const int2* __restrict__ adj, int e) {
    int i = blockIdx.x * blockDim.x + threadIdx.x;
    if (i < e) {
        int2 ed = adj[i];
        int p = atomicAdd(&d_deg[ed.y], 1);
        d_colb[ed.y * CAP + p] = ed.x;
    }
}

// ---------------- one-shot weight split ----------------
__global__ void k_wsplit(const float* __restrict__ W1, const float* __restrict__ W2) {
    int i = blockIdx.x * blockDim.x + threadIdx.x;
    if (i < D * HID) {
        float v = W1[i];
        uint32_t hi = f2tf32(v);
        d_w1h[i] = hi;
        d_w1l[i] = f2tf32(v - __uint_as_float(hi));
    }
    if (i < HID * C) {
        float v = W2[i];
        uint32_t hi = f2tf32(v);
        d_w2h[i] = hi;
        d_w2l[i] = f2tf32(v - __uint_as_float(hi));
    }
}

// ---------------- layer-1 gather (warp per node, fp32 output) ----------------
__global__ void k_agg1(const float* __restrict__ h, int n) {
    int w = (blockIdx.x * blockDim.x + threadIdx.x) >> 5;
    int lane = threadIdx.x & 31;
    if (w >= n) return;
    int half = lane >> 4;
    int q = lane & 15;
    const float4* h4 = (const float4*)h;

    float4 acc = make_float4(0.f, 0.f, 0.f, 0.f);
    if (half == 0) acc = h4[w * 16 + q];          // self-loop
    const int* col = d_colb + w * CAP;
    int end = d_deg[w];
    int j = 0;
    for (; j + 7 < end; j += 8) {
        int s0 = col[j + half];
        int s1 = col[j + 2 + half];
        int s2 = col[j + 4 + half];
        int s3 = col[j + 6 + half];
        float4 v0 = h4[s0 * 16 + q];
        float4 v1 = h4[s1 * 16 + q];
        float4 v2 = h4[s2 * 16 + q];
        float4 v3 = h4[s3 * 16 + q];
        acc.x += (v0.x + v1.x) + (v2.x + v3.x);
        acc.y += (v0.y + v1.y) + (v2.y + v3.y);
        acc.z += (v0.z + v1.z) + (v2.z + v3.z);
        acc.w += (v0.w + v1.w) + (v2.w + v3.w);
    }
    if (j + 3 < end) {
        int s0 = col[j + half];
        int s1 = col[j + 2 + half];
        float4 v0 = h4[s0 * 16 + q];
        float4 v1 = h4[s1 * 16 + q];
        acc.x += v0.x + v1.x;
        acc.y += v0.y + v1.y;
        acc.z += v0.z + v1.z;
        acc.w += v0.w + v1.w;
        j += 4;
    }
    if (j + 1 < end) {
        int s = col[j + half];
        float4 v = h4[s * 16 + q];
        acc.x += v.x; acc.y += v.y; acc.z += v.z; acc.w += v.w;
        j += 2;
    }
    if (j < end && half == 0) {
        int s = col[j];
        float4 v = h4[s * 16 + q];
        acc.x += v.x; acc.y += v.y; acc.z += v.z; acc.w += v.w;
    }
    acc.x += __shfl_xor_sync(0xffffffffu, acc.x, 16);
    acc.y += __shfl_xor_sync(0xffffffffu, acc.y, 16);
    acc.z += __shfl_xor_sync(0xffffffffu, acc.z, 16);
    acc.w += __shfl_xor_sync(0xffffffffu, acc.w, 16);
    if (half == 0)
        ((float4*)d_agg1)[w * 16 + q] = acc;
}

// ---------------- TF32 mma: GEMM1 + ReLU + GEMM2 (64 nodes/block) ----------------
// smem layout (word offsets):
// phase 1: SA_HI 0 [64x68] | SA_LO 4352 [64x68] | W1_HI 8704 [64x136] | W1_LO 17408 [64x136]
// phase 2: X_HI 0 [64x132] | X_LO 8448 [64x132] | W2_HI 16896 [128x40] | W2_LO 22016 [128x40]
#define WO_SA_HI 0
#define WO_SA_LO 4352
#define WO_W1_HI 8704
#define WO_W1_LO 17408
#define WO_X_HI  0
#define WO_X_LO  8448
#define WO_W2_HI 16896
#define WO_W2_LO 22016
#define SM_WORDS 27136
#define SM_BYTES (SM_WORDS * 4)   // 108544

__global__ void __launch_bounds__(256, 2) k_gemm(const float* __restrict__ b1, int n) {
    extern __shared__ uint32_t smw[];
    int tid = threadIdx.x;
    int w = tid >> 5, lane = tid & 31;
    int g = lane >> 2, tg = lane & 3;
    int node0 = blockIdx.x * 64;

    // ---- copy pre-split W1 -> smem [k][136] (uint4, L2-hot) ----
    {
        uint32_t* WH = smw + WO_W1_HI;
        uint32_t* WL = smw + WO_W1_LO;
        const uint4* GH = (const uint4*)d_w1h;
        const uint4* GL = (const uint4*)d_w1l;
#pragma unroll
        for (int i = 0; i < 8; i++) {
            int i4 = tid + i * 256;        // 2048 uint4 total
            int k = i4 >> 5, n4 = i4 & 31;
            *(uint4*)&WH[k * 136 + n4 * 4] = GH[i4];
            *(uint4*)&WL[k * 136 + n4 * 4] = GL[i4];
        }
    }
    // ---- load A tile from fp32 d_agg1, split in-kernel -> AH/AL [node][68] ----
    {
        uint32_t* AH = smw + WO_SA_HI;
        uint32_t* AL = smw + WO_SA_LO;
        int base = node0 * D;
        int lim = (n - node0) * D;
#pragma unroll
        for (int i = 0; i < 16; i++) {
            int idx = tid + i * 256;       // node = idx>>6, k = idx&63
            float v = (idx < lim) ? d_agg1[base + idx] : 0.f;
            uint32_t hi = f2tf32(v);
            int a = (idx >> 6) * 68 + (idx & 63);
            AH[a] = hi;
            AL[a] = f2tf32(v - __uint_as_float(hi));
        }
    }
    __syncthreads();

    // ---- phase 1: x1 = relu(A @ W1 + b1) via tf32 mma (2-split, 3 products) ----
    float c1[8][4];
    {
        const uint32_t* AH = smw + WO_SA_HI;
        const uint32_t* AL = smw + WO_SA_LO;
        const uint32_t* WH = smw + WO_W1_HI;
        const uint32_t* WL = smw + WO_W1_LO;
        int mt = w & 3;
        int nhalf = w >> 2;
#pragma unroll
        for (int nt = 0; nt < 8; nt++)
#pragma unroll
            for (int i = 0; i < 4; i++) c1[nt][i] = 0.f;

#pragma unroll
        for (int kt = 0; kt < 8; kt++) {
            int ar = (mt * 16 + g) * 68 + kt * 8 + tg;
            uint32_t ah0 = AH[ar],     ah1 = AH[ar + 8 * 68];
            uint32_t ah2 = AH[ar + 4], ah3 = AH[ar + 8 * 68 + 4];
            uint32_t al0 = AL[ar],     al1 = AL[ar + 8 * 68];
            uint32_t al2 = AL[ar + 4], al3 = AL[ar + 8 * 68 + 4];
#pragma unroll
            for (int nt = 0; nt < 8; nt++) {
                int br = (kt * 8 + tg) * 136 + nhalf * 64 + nt * 8 + g;
                uint32_t bh0 = WH[br], bh1 = WH[br + 4 * 136];
                uint32_t bl0 = WL[br], bl1 = WL[br + 4 * 136];
                MMA_TF32(c1[nt], ah0, ah1, ah2, ah3, bh0, bh1);
                MMA_TF32(c1[nt], ah0, ah1, ah2, ah3, bl0, bl1);
                MMA_TF32(c1[nt], al0, al1, al2, al3, bh0, bh1);
            }
        }
    }
    __syncthreads();   // SA/W1 reads done -> overlay X

    // ---- write x1 (bias+relu) as tf32 splits into X_HI/X_LO [node][132] ----
    {
        uint32_t* XH = smw + WO_X_HI;
        uint32_t* XL = smw + WO_X_LO;
        int mt = w & 3;
        int nhalf = w >> 2;
#pragma unroll
        for (int nt = 0; nt < 8; nt++) {
            int col = nhalf * 64 + nt * 8 + tg * 2;
            float2 bb = *(const float2*)&b1[col];
#pragma unroll
            for (int ip = 0; ip < 2; ip++) {
                int row = mt * 16 + g + ip * 8;
                float v0 = fmaxf(c1[nt][ip * 2 + 0] + bb.x, 0.f);
                float v1 = fmaxf(c1[nt][ip * 2 + 1] + bb.y, 0.f);
                uint32_t h0 = f2tf32(v0), h1 = f2tf32(v1);
                uint32_t l0 = f2tf32(v0 - __uint_as_float(h0));
                uint32_t l1 = f2tf32(v1 - __uint_as_float(h1));
                *(uint2*)&XH[row * 132 + col] = make_uint2(h0, h1);
                *(uint2*)&XL[row * 132 + col] = make_uint2(l0, l1);
            }
        }
    }
    // ---- copy pre-split W2 (linear [k*40+n], 1280 uint4, L2-hot) ----
    {
        uint32_t* WH = smw + WO_W2_HI;
        uint32_t* WL = smw + WO_W2_LO;
        const uint4* GH = (const uint4*)d_w2h;
        const uint4* GL = (const uint4*)d_w2l;
#pragma unroll
        for (int i = 0; i < 5; i++) {
            int i4 = tid + i * 256;
            ((uint4*)WH)[i4] = GH[i4];
            ((uint4*)WL)[i4] = GL[i4];
        }
    }
    __syncthreads();

    // ---- phase 2: y = x1 @ W2 via tf32 mma; 2-way k-split ----
    float c2[5][4];
    {
        const uint32_t* XH = smw + WO_X_HI;
        const uint32_t* XL = smw + WO_X_LO;
        const uint32_t* WH = smw + WO_W2_HI;
        const uint32_t* WL = smw + WO_W2_LO;
        int mt = w & 3;
        int kh = w >> 2;
#pragma unroll
        for (int nt = 0; nt < 5; nt++)
#pragma unroll
            for (int i = 0; i < 4; i++) c2[nt][i] = 0.f;

#pragma unroll
        for (int kt = 0; kt < 8; kt++) {
            int k0 = kh * 64 + kt * 8;
            int ar = (mt * 16 + g) * 132 + k0 + tg;
            uint32_t ah0 = XH[ar],     ah1 = XH[ar + 8 * 132];
            uint32_t ah2 = XH[ar + 4], ah3 = XH[ar + 8 * 132 + 4];
            uint32_t al0 = XL[ar],     al1 = XL[ar + 8 * 132];
            uint32_t al2 = XL[ar + 4], al3 = XL[ar + 8 * 132 + 4];
#pragma unroll
            for (int nt = 0; nt < 5; nt++) {
                int br = (k0 + tg) * 40 + nt * 8 + g;
                uint32_t bh0 = WH[br], bh1 = WH[br + 4 * 40];
                uint32_t bl0 = WL[br], bl1 = WL[br + 4 * 40];
                MMA_TF32(c2[nt], ah0, ah1, ah2, ah3, bh0, bh1);
                MMA_TF32(c2[nt], ah0, ah1, ah2, ah3, bl0, bl1);
                MMA_TF32(c2[nt], al0, al1, al2, al3, bh0, bh1);
            }
        }
    }
    __syncthreads();

    // ---- reduce k-halves and write y ----
    {
        float* SC = (float*)(smw + WO_X_HI);   // [64][44] scratch
        int mt = w & 3;
        int kh = w >> 2;
        if (kh == 1) {
#pragma unroll
            for (int nt = 0; nt < 5; nt++)
#pragma unroll
                for (int ip = 0; ip < 2; ip++) {
                    int row = mt * 16 + g + ip * 8;
                    int col = nt * 8 + tg * 2;
                    *(float2*)&SC[row * 44 + col] =
                        make_float2(c2[nt][ip * 2], c2[nt][ip * 2 + 1]);
                }
        }
        __syncthreads();
        if (kh == 0) {
#pragma unroll
            for (int nt = 0; nt < 5; nt++)
#pragma unroll
                for (int ip = 0; ip < 2; ip++) {
                    int row = mt * 16 + g + ip * 8;
                    int gn = node0 + row;
                    int col = nt * 8 + tg * 2;
                    float2 o = *(float2*)&SC[row * 44 + col];
                    o.x += c2[nt][ip * 2];
                    o.y += c2[nt][ip * 2 + 1];
                    if (gn < n) *(float2*)&d_y[gn * C + col] = o;
                }
        }
    }
}

// ---------------- layer-2 aggregation + bias + softmax ----------------
__global__ void k_agg2_softmax(const float* __restrict__ b2, float* __restrict__ out, int n) {
    int w = (blockIdx.x * blockDim.x + threadIdx.x) >> 5;
    int lane = threadIdx.x & 31;
    if (w >= n) return;

    int g = lane / 10;
    int q = lane - g * 10;
    bool act = (lane < 30);
    const float4* Y4 = (const float4*)d_y;

    float4 acc = make_float4(0.f, 0.f, 0.f, 0.f);
    if (act && g == 0) acc = Y4[w * 10 + q];

    const int* col = d_colb + w * CAP;
    int end = d_deg[w];
    int j = 0;
    for (; j + 11 < end; j += 12) {
        if (act) {
            int s0 = col[j + g];
            int s1 = col[j + 3 + g];
            int s2 = col[j + 6 + g];
            int s3 = col[j + 9 + g];
            float4 v0 = Y4[s0 * 10 + q];
            float4 v1 = Y4[s1 * 10 + q];
            float4 v2 = Y4[s2 * 10 + q];
            float4 v3 = Y4[s3 * 10 + q];
            acc.x += (v0.x + v1.x) + (v2.x + v3.x);
            acc.y += (v0.y + v1.y) + (v2.y + v3.y);
            acc.z += (v0.z + v1.z) + (v2.z + v3.z);
            acc.w += (v0.w + v1.w) + (v2.w + v3.w);
        }
    }
    if (j + 5 < end) {
        if (act) {
            int s0 = col[j + g];
            int s1 = col[j + 3 + g];
            float4 v0 = Y4[s0 * 10 + q];
            float4 v1 = Y4[s1 * 10 + q];
            acc.x += v0.x + v1.x;
            acc.y += v0.y + v1.y;
            acc.z += v0.z + v1.z;
            acc.w += v0.w + v1.w;
        }
        j += 6;
    }
    if (j + 2 < end) {
        if (act) {
            int s = col[j + g];
            float4 v = Y4[s * 10 + q];
            acc.x += v.x; acc.y += v.y; acc.z += v.z; acc.w += v.w;
        }
        j += 3;
    }
    int rem = end - j;
    if (act && g < rem) {
        int s = col[j + g];
        float4 v = Y4[s * 10 + q];
        acc.x += v.x; acc.y += v.y; acc.z += v.z; acc.w += v.w;
    }

    acc.x += __shfl_sync(0xffffffffu, acc.x, lane + 10) + __shfl_sync(0xffffffffu, acc.x, lane + 20);
    acc.y += __shfl_sync(0xffffffffu, acc.y, lane + 10) + __shfl_sync(0xffffffffu, acc.y, lane + 20);
    acc.z += __shfl_sync(0xffffffffu, acc.z, lane + 10) + __shfl_sync(0xffffffffu, acc.z, lane + 20);
    acc.w += __shfl_sync(0xffffffffu, acc.w, lane + 10) + __shfl_sync(0xffffffffu, acc.w, lane + 20);

    bool own = (lane < 10);
    if (own) {
        acc.x += b2[lane * 4 + 0];
        acc.y += b2[lane * 4 + 1];
        acc.z += b2[lane * 4 + 2];
        acc.w += b2[lane * 4 + 3];
    }
    float m = own ? fmaxf(fmaxf(acc.x, acc.y), fmaxf(acc.z, acc.w)) : -1e30f;
#pragma unroll
    for (int off = 16; off; off >>= 1)
        m = fmaxf(m, __shfl_xor_sync(0xffffffffu, m, off));
    float e0 = __expf(acc.x - m);
    float e1 = __expf(acc.y - m);
    float e2 = __expf(acc.z - m);
    float e3 = __expf(acc.w - m);
    float s = own ? (e0 + e1) + (e2 + e3) : 0.f;
#pragma unroll
    for (int off = 16; off; off >>= 1)
        s += __shfl_xor_sync(0xffffffffu, s, off);
    float inv = 1.f / s;
    if (own) {
        float* o = out + w * C + lane * 4;
        o[0] = e0 * inv;
        o[1] = e1 * inv;
        o[2] = e2 * inv;
        o[3] = e3 * inv;
    }
}

// ---------------- launch ----------------
extern "C" void kernel_launch(void* const* d_in, const int* in_sizes, int n_in,
                              void* d_out, int out_size) {
    const float* h   = (const float*)d_in[0];
    const int*   adj = (const int*)d_in[1];
    const float* W1  = (const float*)d_in[2];
    const float* b1  = (const float*)d_in[3];
    const float* W2  = (const float*)d_in[4];
    const float* b2  = (const float*)d_in[5];
    float* out = (float*)d_out;

    int n = in_sizes[0] / D;
    int e = in_sizes[1] / 2;
    if (n > MAXN) n = MAXN;
    if (e > MAXE) e = MAXE;

    cudaFuncSetAttribute(k_gemm, cudaFuncAttributeMaxDynamicSharedMemorySize, SM_BYTES);

    k_init<<<(n + 255) / 256, 256>>>(n);
    k_build<<<(e + 255) / 256, 256>>>((const int2*)adj, e);
    k_wsplit<<<(D * HID + 255) / 256, 256>>>(W1, W2);

    k_agg1<<<(n * 32 + 255) / 256, 256>>>(h, n);
    k_gemm<<<(n + 63) / 64, 256, SM_BYTES>>>(b1, n);
    k_agg2_softmax<<<(n * 32 + 255) / 256, 256>>>(b2, out, n);
}

// round 16
// speedup vs baseline: 1.3191x; 1.2548x over previous
#include <cuda_runtime.h>
#include <cuda_bf16.h>
#include <math.h>
#include <cstdint>

#define MAXN 100000
#define MAXE 1200000
#define D    64
#define HID  128
#define C    40
#define CAP  128

// ---------------- device scratch ----------------
__device__ int      d_deg[MAXN];
__device__ int      d_colb[(size_t)MAXN * CAP];
__device__ __align__(16) float d_agg1[(size_t)MAXN * D];     // 25.6 MB fp32
__device__ __align__(16) uint32_t d_w1h[(D / 2) * HID];      // packed bf16 pairs along k
__device__ __align__(16) uint32_t d_w1l[(D / 2) * HID];
__device__ __align__(16) uint32_t d_w2h[(HID / 2) * C];
__device__ __align__(16) uint32_t d_w2l[(HID / 2) * C];
__device__ __align__(16) float d_y[(size_t)MAXN * C];

// ---------------- bf16 helpers ----------------
__device__ __forceinline__ void bfsplit2(float x, float y, uint32_t& hi, uint32_t& lo) {
    __nv_bfloat162 h = __floats2bfloat162_rn(x, y);   // .x = x (low), .y = y (high)
    float rx = x - __bfloat162float(h.x);
    float ry = y - __bfloat162float(h.y);
    __nv_bfloat162 l = __floats2bfloat162_rn(rx, ry);
    hi = *(uint32_t*)&h;
    lo = *(uint32_t*)&l;
}
#define MMA_BF16(cc, a0, a1, a2, a3, b0, b1) \
    asm volatile("mma.sync.aligned.m16n8k16.row.col.f32.bf16.bf16.f32 " \
        "{%0,%1,%2,%3}, {%4,%5,%6,%7}, {%8,%9}, {%0,%1,%2,%3};" \
        : "+f"((cc)[0]), "+f"((cc)[1]), "+f"((cc)[2]), "+f"((cc)[3]) \
        : "r"(a0), "r"(a1), "r"(a2), "r"(a3), "r"(b0), "r"(b1))

// ---------------- build ----------------
__global__ void k_init(int n) {
    int i = blockIdx.x * blockDim.x + threadIdx.x;
    if (i < n) d_deg[i] = 0;
}

__global__ void k_build(const int2* __restrict__ adj, int e) {
    int i = blockIdx.x * blockDim.x + threadIdx.x;
    if (i < e) {
        int2 ed = adj[i];
        int p = atomicAdd(&d_deg[ed.y], 1);
        d_colb[ed.y * CAP + p] = ed.x;
    }
}

// ---------------- one-shot weight split (packed bf16 pairs along k) ----------------
__global__ void k_wsplit(const float* __restrict__ W1, const float* __restrict__ W2) {
    int i = blockIdx.x * blockDim.x + threadIdx.x;
    if (i < (D / 2) * HID) {          // 4096 pairs: kk = i / HID, n = i % HID
        int kk = i >> 7, nn = i & 127;
        float a = W1[(2 * kk) * HID + nn];
        float b = W1[(2 * kk + 1) * HID + nn];
        uint32_t hi, lo;
        bfsplit2(a, b, hi, lo);
        d_w1h[i] = hi;
        d_w1l[i] = lo;
    }
    if (i < (HID / 2) * C) {          // 2560 pairs: kk = i / C, n = i % C
        int kk = i / C, nn = i - kk * C;
        float a = W2[(2 * kk) * C + nn];
        float b = W2[(2 * kk + 1) * C + nn];
        uint32_t hi, lo;
        bfsplit2(a, b, hi, lo);
        d_w2h[i] = hi;
        d_w2l[i] = lo;
    }
}

// ---------------- layer-1 gather (warp per node, fp32 output) ----------------
__global__ void k_agg1(const float* __restrict__ h, int n) {
    int w = (blockIdx.x * blockDim.x + threadIdx.x) >> 5;
    int lane = threadIdx.x & 31;
    if (w >= n) return;
    int half = lane >> 4;
    int q = lane & 15;
    const float4* h4 = (const float4*)h;

    float4 acc = make_float4(0.f, 0.f, 0.f, 0.f);
    if (half == 0) acc = h4[w * 16 + q];
    const int* col = d_colb + w * CAP;
    int end = d_deg[w];
    int j = 0;
    for (; j + 7 < end; j += 8) {
        int s0 = col[j + half];
        int s1 = col[j + 2 + half];
        int s2 = col[j + 4 + half];
        int s3 = col[j + 6 + half];
        float4 v0 = h4[s0 * 16 + q];
        float4 v1 = h4[s1 * 16 + q];
        float4 v2 = h4[s2 * 16 + q];
        float4 v3 = h4[s3 * 16 + q];
        acc.x += (v0.x + v1.x) + (v2.x + v3.x);
        acc.y += (v0.y + v1.y) + (v2.y + v3.y);
        acc.z += (v0.z + v1.z) + (v2.z + v3.z);
        acc.w += (v0.w + v1.w) + (v2.w + v3.w);
    }
    if (j + 3 < end) {
        int s0 = col[j + half];
        int s1 = col[j + 2 + half];
        float4 v0 = h4[s0 * 16 + q];
        float4 v1 = h4[s1 * 16 + q];
        acc.x += v0.x + v1.x;
        acc.y += v0.y + v1.y;
        acc.z += v0.z + v1.z;
        acc.w += v0.w + v1.w;
        j += 4;
    }
    if (j + 1 < end) {
        int s = col[j + half];
        float4 v = h4[s * 16 + q];
        acc.x += v.x; acc.y += v.y; acc.z += v.z; acc.w += v.w;
        j += 2;
    }
    if (j < end && half == 0) {
        int s = col[j];
        float4 v = h4[s * 16 + q];
        acc.x += v.x; acc.y += v.y; acc.z += v.z; acc.w += v.w;
    }
    acc.x += __shfl_xor_sync(0xffffffffu, acc.x, 16);
    acc.y += __shfl_xor_sync(0xffffffffu, acc.y, 16);
    acc.z += __shfl_xor_sync(0xffffffffu, acc.z, 16);
    acc.w += __shfl_xor_sync(0xffffffffu, acc.w, 16);
    if (half == 0)
        ((float4*)d_agg1)[w * 16 + q] = acc;
}

// ---------------- bf16 mma: GEMM1 + ReLU + GEMM2 (64 nodes/block) ----------------
// packed-pair word layouts (word offsets):
// phase 1: AH 0 [64x36] | AL 2304 [64x36] | W1H 4608 [32x136] | W1L 8960 [32x136]  (end 13312)
// phase 2: XH 0 [64x68] | XL 4352 [64x68] | W2H 8704 [64x40]  | W2L 11264 [64x40]  (end 13824)
#define WO_AH   0
#define WO_AL   2304
#define WO_W1H  4608
#define WO_W1L  8960
#define WO_XH   0
#define WO_XL   4352
#define WO_W2H  8704
#define WO_W2L  11264
#define SM_WORDS 13824
#define SM_BYTES (SM_WORDS * 4)   // 55296

__global__ void __launch_bounds__(256, 3) k_gemm(const float* __restrict__ b1, int n) {
    extern __shared__ uint32_t smw[];
    int tid = threadIdx.x;
    int w = tid >> 5, lane = tid & 31;
    int g = lane >> 2, tg = lane & 3;
    int node0 = blockIdx.x * 64;

    // ---- copy pre-split W1 -> smem [kk][136] (uint4; 1024 uint4 per array) ----
    {
        uint32_t* WH = smw + WO_W1H;
        uint32_t* WL = smw + WO_W1L;
        const uint4* GH = (const uint4*)d_w1h;
        const uint4* GL = (const uint4*)d_w1l;
#pragma unroll
        for (int i = 0; i < 4; i++) {
            int i4 = tid + i * 256;
            int kk = i4 >> 5, n4 = i4 & 31;
            *(uint4*)&WH[kk * 136 + n4 * 4] = GH[i4];
            *(uint4*)&WL[kk * 136 + n4 * 4] = GL[i4];
        }
    }
    // ---- load A tile from fp32 d_agg1, split packed -> AH/AL [node][36] ----
    {
        uint32_t* AH = smw + WO_AH;
        uint32_t* AL = smw + WO_AL;
        const float2* G2 = (const float2*)d_agg1 + node0 * 32;
        int lim = (n - node0) * 32;    // pairs in range
#pragma unroll
        for (int i = 0; i < 8; i++) {
            int p = tid + i * 256;     // node = p>>5, kk = p&31
            float2 v = make_float2(0.f, 0.f);
            if (p < lim) v = G2[p];
            uint32_t hi, lo;
            bfsplit2(v.x, v.y, hi, lo);
            int a = (p >> 5) * 36 + (p & 31);
            AH[a] = hi;
            AL[a] = lo;
        }
    }
    __syncthreads();

    // ---- phase 1: x1 = relu(A @ W1 + b1) via bf16 mma (2-split, 3 products) ----
    float c1[8][4];
    {
        const uint32_t* AH = smw + WO_AH;
        const uint32_t* AL = smw + WO_AL;
        const uint32_t* WH = smw + WO_W1H;
        const uint32_t* WL = smw + WO_W1L;
        int mt = w & 3;
        int nhalf = w >> 2;
#pragma unroll
        for (int nt = 0; nt < 8; nt++)
#pragma unroll
            for (int i = 0; i < 4; i++) c1[nt][i] = 0.f;

#pragma unroll
        for (int kt = 0; kt < 4; kt++) {             // K16 chunks: k = kt*16..+15
            int ar = (mt * 16 + g) * 36 + kt * 8 + tg;
            uint32_t ah0 = AH[ar],     ah1 = AH[ar + 8 * 36];
            uint32_t ah2 = AH[ar + 4], ah3 = AH[ar + 8 * 36 + 4];
            uint32_t al0 = AL[ar],     al1 = AL[ar + 8 * 36];
            uint32_t al2 = AL[ar + 4], al3 = AL[ar + 8 * 36 + 4];
#pragma unroll
            for (int nt = 0; nt < 8; nt++) {
                int br = (kt * 8 + tg) * 136 + nhalf * 64 + nt * 8 + g;
                uint32_t bh0 = WH[br], bh1 = WH[br + 4 * 136];
                uint32_t bl0 = WL[br], bl1 = WL[br + 4 * 136];
                MMA_BF16(c1[nt], ah0, ah1, ah2, ah3, bh0, bh1);
                MMA_BF16(c1[nt], ah0, ah1, ah2, ah3, bl0, bl1);
                MMA_BF16(c1[nt], al0, al1, al2, al3, bh0, bh1);
            }
        }
    }
    __syncthreads();   // A/W1 reads done -> overlay X

    // ---- write x1 (bias+relu) packed bf16 splits -> XH/XL [node][68] ----
    {
        uint32_t* XH = smw + WO_XH;
        uint32_t* XL = smw + WO_XL;
        int mt = w & 3;
        int nhalf = w >> 2;
#pragma unroll
        for (int nt = 0; nt < 8; nt++) {
            int col = nhalf * 64 + nt * 8 + tg * 2;
            float2 bb = *(const float2*)&b1[col];
            int wcol = nhalf * 32 + nt * 4 + tg;      // packed word col
#pragma unroll
            for (int ip = 0; ip < 2; ip++) {
                int row = mt * 16 + g + ip * 8;
                float v0 = fmaxf(c1[nt][ip * 2 + 0] + bb.x, 0.f);
                float v1 = fmaxf(c1[nt][ip * 2 + 1] + bb.y, 0.f);
                uint32_t hi, lo;
                bfsplit2(v0, v1, hi, lo);
                XH[row * 68 + wcol] = hi;
                XL[row * 68 + wcol] = lo;
            }
        }
    }
    // ---- copy pre-split W2 (2560 words = 640 uint4, linear) ----
    {
        uint32_t* WH = smw + WO_W2H;
        uint32_t* WL = smw + WO_W2L;
        const uint4* GH = (const uint4*)d_w2h;
        const uint4* GL = (const uint4*)d_w2l;
#pragma unroll
        for (int i = 0; i < 3; i++) {
            int i4 = tid + i * 256;
            if (i4 < 640) {
                ((uint4*)WH)[i4] = GH[i4];
                ((uint4*)WL)[i4] = GL[i4];
            }
        }
    }
    __syncthreads();

    // ---- phase 2: y = x1 @ W2 via bf16 mma; 2-way k-split ----
    float c2[5][4];
    {
        const uint32_t* XH = smw + WO_XH;
        const uint32_t* XL = smw + WO_XL;
        const uint32_t* WH = smw + WO_W2H;
        const uint32_t* WL = smw + WO_W2L;
        int mt = w & 3;
        int kh = w >> 2;
#pragma unroll
        for (int nt = 0; nt < 5; nt++)
#pragma unroll
            for (int i = 0; i < 4; i++) c2[nt][i] = 0.f;

#pragma unroll
        for (int kt = 0; kt < 4; kt++) {
            int kk0 = kh * 32 + kt * 8;
            int ar = (mt * 16 + g) * 68 + kk0 + tg;
            uint32_t ah0 = XH[ar],     ah1 = XH[ar + 8 * 68];
            uint32_t ah2 = XH[ar + 4], ah3 = XH[ar + 8 * 68 + 4];
            uint32_t al0 = XL[ar],     al1 = XL[ar + 8 * 68];
            uint32_t al2 = XL[ar + 4], al3 = XL[ar + 8 * 68 + 4];
#pragma unroll
            for (int nt = 0; nt < 5; nt++) {
                int br = (kk0 + tg) * 40 + nt * 8 + g;
                uint32_t bh0 = WH[br], bh1 = WH[br + 4 * 40];
                uint32_t bl0 = WL[br], bl1 = WL[br + 4 * 40];
                MMA_BF16(c2[nt], ah0, ah1, ah2, ah3, bh0, bh1);
                MMA_BF16(c2[nt], ah0, ah1, ah2, ah3, bl0, bl1);
                MMA_BF16(c2[nt], al0, al1, al2, al3, bh0, bh1);
            }
        }
    }
    __syncthreads();

    // ---- reduce k-halves and write y ----
    {
        float* SC = (float*)(smw + WO_XH);   // [64][44] scratch (2816 words)
        int mt = w & 3;
        int kh = w >> 2;
        if (kh == 1) {
#pragma unroll
            for (int nt = 0; nt < 5; nt++)
#pragma unroll
                for (int ip = 0; ip < 2; ip++) {
                    int row = mt * 16 + g + ip * 8;
                    int col = nt * 8 + tg * 2;
                    *(float2*)&SC[row * 44 + col] =
                        make_float2(c2[nt][ip * 2], c2[nt][ip * 2 + 1]);
                }
        }
        __syncthreads();
        if (kh == 0) {
#pragma unroll
            for (int nt = 0; nt < 5; nt++)
#pragma unroll
                for (int ip = 0; ip < 2; ip++) {
                    int row = mt * 16 + g + ip * 8;
                    int gn = node0 + row;
                    int col = nt * 8 + tg * 2;
                    float2 o = *(float2*)&SC[row * 44 + col];
                    o.x += c2[nt][ip * 2];
                    o.y += c2[nt][ip * 2 + 1];
                    if (gn < n) *(float2*)&d_y[gn * C + col] = o;
                }
        }
    }
}

// ---------------- layer-2 aggregation + bias + softmax ----------------
__global__ void k_agg2_softmax(const float* __restrict__ b2, float* __restrict__ out, int n) {
    int w = (blockIdx.x * blockDim.x + threadIdx.x) >> 5;
    int lane = threadIdx.x & 31;
    if (w >= n) return;

    int g = lane / 10;
    int q = lane - g * 10;
    bool act = (lane < 30);
    const float4* Y4 = (const float4*)d_y;

    float4 acc = make_float4(0.f, 0.f, 0.f, 0.f);
    if (act && g == 0) acc = Y4[w * 10 + q];

    const int* col = d_colb + w * CAP;
    int end = d_deg[w];
    int j = 0;
    for (; j + 11 < end; j += 12) {
        if (act) {
            int s0 = col[j + g];
            int s1 = col[j + 3 + g];
            int s2 = col[j + 6 + g];
            int s3 = col[j + 9 + g];
            float4 v0 = Y4[s0 * 10 + q];
            float4 v1 = Y4[s1 * 10 + q];
            float4 v2 = Y4[s2 * 10 + q];
            float4 v3 = Y4[s3 * 10 + q];
            acc.x += (v0.x + v1.x) + (v2.x + v3.x);
            acc.y += (v0.y + v1.y) + (v2.y + v3.y);
            acc.z += (v0.z + v1.z) + (v2.z + v3.z);
            acc.w += (v0.w + v1.w) + (v2.w + v3.w);
        }
    }
    if (j + 5 < end) {
        if (act) {
            int s0 = col[j + g];
            int s1 = col[j + 3 + g];
            float4 v0 = Y4[s0 * 10 + q];
            float4 v1 = Y4[s1 * 10 + q];
            acc.x += v0.x + v1.x;
            acc.y += v0.y + v1.y;
            acc.z += v0.z + v1.z;
            acc.w += v0.w + v1.w;
        }
        j += 6;
    }
    if (j + 2 < end) {
        if (act) {
            int s = col[j + g];
            float4 v = Y4[s * 10 + q];
            acc.x += v.x; acc.y += v.y; acc.z += v.z; acc.w += v.w;
        }
        j += 3;
    }
    int rem = end - j;
    if (act && g < rem) {
        int s = col[j + g];
        float4 v = Y4[s * 10 + q];
        acc.x += v.x; acc.y += v.y; acc.z += v.z; acc.w += v.w;
    }

    acc.x += __shfl_sync(0xffffffffu, acc.x, lane + 10) + __shfl_sync(0xffffffffu, acc.x, lane + 20);
    acc.y += __shfl_sync(0xffffffffu, acc.y, lane + 10) + __shfl_sync(0xffffffffu, acc.y, lane + 20);
    acc.z += __shfl_sync(0xffffffffu, acc.z, lane + 10) + __shfl_sync(0xffffffffu, acc.z, lane + 20);
    acc.w += __shfl_sync(0xffffffffu, acc.w, lane + 10) + __shfl_sync(0xffffffffu, acc.w, lane + 20);

    bool own = (lane < 10);
    if (own) {
        acc.x += b2[lane * 4 + 0];
        acc.y += b2[lane * 4 + 1];
        acc.z += b2[lane * 4 + 2];
        acc.w += b2[lane * 4 + 3];
    }
    float m = own ? fmaxf(fmaxf(acc.x, acc.y), fmaxf(acc.z, acc.w)) : -1e30f;
#pragma unroll
    for (int off = 16; off; off >>= 1)
        m = fmaxf(m, __shfl_xor_sync(0xffffffffu, m, off));
    float e0 = __expf(acc.x - m);
    float e1 = __expf(acc.y - m);
    float e2 = __expf(acc.z - m);
    float e3 = __expf(acc.w - m);
    float s = own ? (e0 + e1) + (e2 + e3) : 0.f;
#pragma unroll
    for (int off = 16; off; off >>= 1)
        s += __shfl_xor_sync(0xffffffffu, s, off);
    float inv = 1.f / s;
    if (own) {
        float* o = out + w * C + lane * 4;
        o[0] = e0 * inv;
        o[1] = e1 * inv;
        o[2] = e2 * inv;
        o[3] = e3 * inv;
    }
}

// ---------------- launch ----------------
extern "C" void kernel_launch(void* const* d_in, const int* in_sizes, int n_in,
                              void* d_out, int out_size) {
    const float* h   = (const float*)d_in[0];
    const int*   adj = (const int*)d_in[1];
    const float* W1  = (const float*)d_in[2];
    const float* b1  = (const float*)d_in[3];
    const float* W2  = (const float*)d_in[4];
    const float* b2  = (const float*)d_in[5];
    float* out = (float*)d_out;

    int n = in_sizes[0] / D;
    int e = in_sizes[1] / 2;
    if (n > MAXN) n = MAXN;
    if (e > MAXE) e = MAXE;

    cudaFuncSetAttribute(k_gemm, cudaFuncAttributeMaxDynamicSharedMemorySize, SM_BYTES);

    k_init<<<(n + 255) / 256, 256>>>(n);
    k_build<<<(e + 255) / 256, 256>>>((const int2*)adj, e);
    k_wsplit<<<((D / 2) * HID + 255) / 256, 256>>>(W1, W2);

    k_agg1<<<(n * 32 + 255) / 256, 256>>>(h, n);
    k_gemm<<<(n + 63) / 64, 256, SM_BYTES>>>(b1, n);
    k_agg2_softmax<<<(n * 32 + 255) / 256, 256>>>(b2, out, n);
}

// round 17
// speedup vs baseline: 1.3469x; 1.0210x over previous
#include <cuda_runtime.h>
#include <cuda_bf16.h>
#include <math.h>
#include <cstdint>

#define MAXN 100000
#define MAXE 1200000
#define D    64
#define HID  128
#define C    40
#define CAP  64       // max deg for Poisson(12) over 100K nodes ~ 40; P(>=64) ~ 1e-30

// ---------------- device scratch ----------------
__device__ int      d_deg[MAXN];
__device__ int      d_colb[(size_t)MAXN * CAP];              // 25.6 MB
__device__ __align__(16) float d_agg1[(size_t)MAXN * D];     // 25.6 MB fp32
__device__ __align__(16) uint32_t d_w1h[(D / 2) * HID];      // packed bf16 pairs along k
__device__ __align__(16) uint32_t d_w1l[(D / 2) * HID];
__device__ __align__(16) uint32_t d_w2h[(HID / 2) * C];
__device__ __align__(16) uint32_t d_w2l[(HID / 2) * C];
__device__ __align__(16) float d_y[(size_t)MAXN * C];

// ---------------- bf16 helpers ----------------
__device__ __forceinline__ void bfsplit2(float x, float y, uint32_t& hi, uint32_t& lo) {
    __nv_bfloat162 h = __floats2bfloat162_rn(x, y);
    float rx = x - __bfloat162float(h.x);
    float ry = y - __bfloat162float(h.y);
    __nv_bfloat162 l = __floats2bfloat162_rn(rx, ry);
    hi = *(uint32_t*)&h;
    lo = *(uint32_t*)&l;
}
#define MMA_BF16(cc, a0, a1, a2, a3, b0, b1) \
    asm volatile("mma.sync.aligned.m16n8k16.row.col.f32.bf16.bf16.f32 " \
        "{%0,%1,%2,%3}, {%4,%5,%6,%7}, {%8,%9}, {%0,%1,%2,%3};" \
        : "+f"((cc)[0]), "+f"((cc)[1]), "+f"((cc)[2]), "+f"((cc)[3]) \
        : "r"(a0), "r"(a1), "r"(a2), "r"(a3), "r"(b0), "r"(b1))

// ---------------- prep: zero degrees + split weights (one launch) ----------------
__global__ void k_prep(const float* __restrict__ W1, const float* __restrict__ W2, int n) {
    int i = blockIdx.x * blockDim.x + threadIdx.x;
    if (i < n) d_deg[i] = 0;
    if (i < (D / 2) * HID) {          // 4096 pairs: kk = i >> 7, nn = i & 127
        int kk = i >> 7, nn = i & 127;
        float a = W1[(2 * kk) * HID + nn];
        float b = W1[(2 * kk + 1) * HID + nn];
        uint32_t hi, lo;
        bfsplit2(a, b, hi, lo);
        d_w1h[i] = hi;
        d_w1l[i] = lo;
    }
    if (i < (HID / 2) * C) {          // 2560 pairs
        int kk = i / C, nn = i - kk * C;
        float a = W2[(2 * kk) * C + nn];
        float b = W2[(2 * kk + 1) * C + nn];
        uint32_t hi, lo;
        bfsplit2(a, b, hi, lo);
        d_w2h[i] = hi;
        d_w2l[i] = lo;
    }
}

__global__ void k_build(const int2* __restrict__ adj, int e) {
    int i = blockIdx.x * blockDim.x + threadIdx.x;
    if (i < e) {
        int2 ed = adj[i];
        int p = atomicAdd(&d_deg[ed.y], 1);
        d_colb[ed.y * CAP + p] = ed.x;
    }
}

// ---------------- layer-1 gather: half-warp per node (2 nodes/warp) ----------------
__global__ void k_agg1(const float* __restrict__ h, int n) {
    int hw = (blockIdx.x * blockDim.x + threadIdx.x) >> 4;   // half-warp id = node
    int q = threadIdx.x & 15;
    if (hw >= n) return;
    const float4* h4 = (const float4*)h;

    float4 acc = h4[hw * 16 + q];                 // self-loop
    const int* col = d_colb + hw * CAP;
    int end = d_deg[hw];
    int j = 0;
    for (; j + 3 < end; j += 4) {                 // 4 independent loads in flight
        int s0 = col[j];
        int s1 = col[j + 1];
        int s2 = col[j + 2];
        int s3 = col[j + 3];
        float4 v0 = h4[s0 * 16 + q];
        float4 v1 = h4[s1 * 16 + q];
        float4 v2 = h4[s2 * 16 + q];
        float4 v3 = h4[s3 * 16 + q];
        acc.x += (v0.x + v1.x) + (v2.x + v3.x);
        acc.y += (v0.y + v1.y) + (v2.y + v3.y);
        acc.z += (v0.z + v1.z) + (v2.z + v3.z);
        acc.w += (v0.w + v1.w) + (v2.w + v3.w);
    }
    if (j + 1 < end) {
        int s0 = col[j];
        int s1 = col[j + 1];
        float4 v0 = h4[s0 * 16 + q];
        float4 v1 = h4[s1 * 16 + q];
        acc.x += v0.x + v1.x;
        acc.y += v0.y + v1.y;
        acc.z += v0.z + v1.z;
        acc.w += v0.w + v1.w;
        j += 2;
    }
    if (j < end) {
        int s = col[j];
        float4 v = h4[s * 16 + q];
        acc.x += v.x; acc.y += v.y; acc.z += v.z; acc.w += v.w;
    }
    ((float4*)d_agg1)[hw * 16 + q] = acc;
}

// ---------------- bf16 mma: GEMM1 + ReLU + GEMM2 (64 nodes/block) ----------------
#define WO_AH   0
#define WO_AL   2304
#define WO_W1H  4608
#define WO_W1L  8960
#define WO_XH   0
#define WO_XL   4352
#define WO_W2H  8704
#define WO_W2L  11264
#define SM_WORDS 13824
#define SM_BYTES (SM_WORDS * 4)   // 55296

__global__ void __launch_bounds__(256, 3) k_gemm(const float* __restrict__ b1, int n) {
    extern __shared__ uint32_t smw[];
    int tid = threadIdx.x;
    int w = tid >> 5, lane = tid & 31;
    int g = lane >> 2, tg = lane & 3;
    int node0 = blockIdx.x * 64;

    // ---- copy pre-split W1 -> smem [kk][136] (uint4) ----
    {
        uint32_t* WH = smw + WO_W1H;
        uint32_t* WL = smw + WO_W1L;
        const uint4* GH = (const uint4*)d_w1h;
        const uint4* GL = (const uint4*)d_w1l;
#pragma unroll
        for (int i = 0; i < 4; i++) {
            int i4 = tid + i * 256;
            int kk = i4 >> 5, n4 = i4 & 31;
            *(uint4*)&WH[kk * 136 + n4 * 4] = GH[i4];
            *(uint4*)&WL[kk * 136 + n4 * 4] = GL[i4];
        }
    }
    // ---- load A tile from fp32 d_agg1, split packed -> AH/AL [node][36] ----
    {
        uint32_t* AH = smw + WO_AH;
        uint32_t* AL = smw + WO_AL;
        const float2* G2 = (const float2*)d_agg1 + node0 * 32;
        int lim = (n - node0) * 32;
#pragma unroll
        for (int i = 0; i < 8; i++) {
            int p = tid + i * 256;
            float2 v = make_float2(0.f, 0.f);
            if (p < lim) v = G2[p];
            uint32_t hi, lo;
            bfsplit2(v.x, v.y, hi, lo);
            int a = (p >> 5) * 36 + (p & 31);
            AH[a] = hi;
            AL[a] = lo;
        }
    }
    __syncthreads();

    // ---- phase 1: x1 = relu(A @ W1 + b1) via bf16 mma (2-split, 3 products) ----
    float c1[8][4];
    {
        const uint32_t* AH = smw + WO_AH;
        const uint32_t* AL = smw + WO_AL;
        const uint32_t* WH = smw + WO_W1H;
        const uint32_t* WL = smw + WO_W1L;
        int mt = w & 3;
        int nhalf = w >> 2;
#pragma unroll
        for (int nt = 0; nt < 8; nt++)
#pragma unroll
            for (int i = 0; i < 4; i++) c1[nt][i] = 0.f;

#pragma unroll
        for (int kt = 0; kt < 4; kt++) {
            int ar = (mt * 16 + g) * 36 + kt * 8 + tg;
            uint32_t ah0 = AH[ar],     ah1 = AH[ar + 8 * 36];
            uint32_t ah2 = AH[ar + 4], ah3 = AH[ar + 8 * 36 + 4];
            uint32_t al0 = AL[ar],     al1 = AL[ar + 8 * 36];
            uint32_t al2 = AL[ar + 4], al3 = AL[ar + 8 * 36 + 4];
#pragma unroll
            for (int nt = 0; nt < 8; nt++) {
                int br = (kt * 8 + tg) * 136 + nhalf * 64 + nt * 8 + g;
                uint32_t bh0 = WH[br], bh1 = WH[br + 4 * 136];
                uint32_t bl0 = WL[br], bl1 = WL[br + 4 * 136];
                MMA_BF16(c1[nt], ah0, ah1, ah2, ah3, bh0, bh1);
                MMA_BF16(c1[nt], ah0, ah1, ah2, ah3, bl0, bl1);
                MMA_BF16(c1[nt], al0, al1, al2, al3, bh0, bh1);
            }
        }
    }
    __syncthreads();

    // ---- write x1 (bias+relu) packed bf16 splits -> XH/XL [node][68] ----
    {
        uint32_t* XH = smw + WO_XH;
        uint32_t* XL = smw + WO_XL;
        int mt = w & 3;
        int nhalf = w >> 2;
#pragma unroll
        for (int nt = 0; nt < 8; nt++) {
            int col = nhalf * 64 + nt * 8 + tg * 2;
            float2 bb = *(const float2*)&b1[col];
            int wcol = nhalf * 32 + nt * 4 + tg;
#pragma unroll
            for (int ip = 0; ip < 2; ip++) {
                int row = mt * 16 + g + ip * 8;
                float v0 = fmaxf(c1[nt][ip * 2 + 0] + bb.x, 0.f);
                float v1 = fmaxf(c1[nt][ip * 2 + 1] + bb.y, 0.f);
                uint32_t hi, lo;
                bfsplit2(v0, v1, hi, lo);
                XH[row * 68 + wcol] = hi;
                XL[row * 68 + wcol] = lo;
            }
        }
    }
    // ---- copy pre-split W2 (640 uint4) ----
    {
        uint32_t* WH = smw + WO_W2H;
        uint32_t* WL = smw + WO_W2L;
        const uint4* GH = (const uint4*)d_w2h;
        const uint4* GL = (const uint4*)d_w2l;
#pragma unroll
        for (int i = 0; i < 3; i++) {
            int i4 = tid + i * 256;
            if (i4 < 640) {
                ((uint4*)WH)[i4] = GH[i4];
                ((uint4*)WL)[i4] = GL[i4];
            }
        }
    }
    __syncthreads();

    // ---- phase 2: y = x1 @ W2 via bf16 mma; 2-way k-split ----
    float c2[5][4];
    {
        const uint32_t* XH = smw + WO_XH;
        const uint32_t* XL = smw + WO_XL;
        const uint32_t* WH = smw + WO_W2H;
        const uint32_t* WL = smw + WO_W2L;
        int mt = w & 3;
        int kh = w >> 2;
#pragma unroll
        for (int nt = 0; nt < 5; nt++)
#pragma unroll
            for (int i = 0; i < 4; i++) c2[nt][i] = 0.f;

#pragma unroll
        for (int kt = 0; kt < 4; kt++) {
            int kk0 = kh * 32 + kt * 8;
            int ar = (mt * 16 + g) * 68 + kk0 + tg;
            uint32_t ah0 = XH[ar],     ah1 = XH[ar + 8 * 68];
            uint32_t ah2 = XH[ar + 4], ah3 = XH[ar + 8 * 68 + 4];
            uint32_t al0 = XL[ar],     al1 = XL[ar + 8 * 68];
            uint32_t al2 = XL[ar + 4], al3 = XL[ar + 8 * 68 + 4];
#pragma unroll
            for (int nt = 0; nt < 5; nt++) {
                int br = (kk0 + tg) * 40 + nt * 8 + g;
                uint32_t bh0 = WH[br], bh1 = WH[br + 4 * 40];
                uint32_t bl0 = WL[br], bl1 = WL[br + 4 * 40];
                MMA_BF16(c2[nt], ah0, ah1, ah2, ah3, bh0, bh1);
                MMA_BF16(c2[nt], ah0, ah1, ah2, ah3, bl0, bl1);
                MMA_BF16(c2[nt], al0, al1, al2, al3, bh0, bh1);
            }
        }
    }
    __syncthreads();

    // ---- reduce k-halves and write y ----
    {
        float* SC = (float*)(smw + WO_XH);
        int mt = w & 3;
        int kh = w >> 2;
        if (kh == 1) {
#pragma unroll
            for (int nt = 0; nt < 5; nt++)
#pragma unroll
                for (int ip = 0; ip < 2; ip++) {
                    int row = mt * 16 + g + ip * 8;
                    int col = nt * 8 + tg * 2;
                    *(float2*)&SC[row * 44 + col] =
                        make_float2(c2[nt][ip * 2], c2[nt][ip * 2 + 1]);
                }
        }
        __syncthreads();
        if (kh == 0) {
#pragma unroll
            for (int nt = 0; nt < 5; nt++)
#pragma unroll
                for (int ip = 0; ip < 2; ip++) {
                    int row = mt * 16 + g + ip * 8;
                    int gn = node0 + row;
                    int col = nt * 8 + tg * 2;
                    float2 o = *(float2*)&SC[row * 44 + col];
                    o.x += c2[nt][ip * 2];
                    o.y += c2[nt][ip * 2 + 1];
                    if (gn < n) *(float2*)&d_y[gn * C + col] = o;
                }
        }
    }
}

// ---------------- layer-2 aggregation + bias + softmax ----------------
__global__ void k_agg2_softmax(const float* __restrict__ b2, float* __restrict__ out, int n) {
    int w = (blockIdx.x * blockDim.x + threadIdx.x) >> 5;
    int lane = threadIdx.x & 31;
    if (w >= n) return;

    int g = lane / 10;
    int q = lane - g * 10;
    bool act = (lane < 30);
    const float4* Y4 = (const float4*)d_y;

    float4 acc = make_float4(0.f, 0.f, 0.f, 0.f);
    if (act && g == 0) acc = Y4[w * 10 + q];

    const int* col = d_colb + w * CAP;
    int end = d_deg[w];
    int j = 0;
    for (; j + 11 < end; j += 12) {
        if (act) {
            int s0 = col[j + g];
            int s1 = col[j + 3 + g];
            int s2 = col[j + 6 + g];
            int s3 = col[j + 9 + g];
            float4 v0 = Y4[s0 * 10 + q];
            float4 v1 = Y4[s1 * 10 + q];
            float4 v2 = Y4[s2 * 10 + q];
            float4 v3 = Y4[s3 * 10 + q];
            acc.x += (v0.x + v1.x) + (v2.x + v3.x);
            acc.y += (v0.y + v1.y) + (v2.y + v3.y);
            acc.z += (v0.z + v1.z) + (v2.z + v3.z);
            acc.w += (v0.w + v1.w) + (v2.w + v3.w);
        }
    }
    if (j + 5 < end) {
        if (act) {
            int s0 = col[j + g];
            int s1 = col[j + 3 + g];
            float4 v0 = Y4[s0 * 10 + q];
            float4 v1 = Y4[s1 * 10 + q];
            acc.x += v0.x + v1.x;
            acc.y += v0.y + v1.y;
            acc.z += v0.z + v1.z;
            acc.w += v0.w + v1.w;
        }
        j += 6;
    }
    if (j + 2 < end) {
        if (act) {
            int s = col[j + g];
            float4 v = Y4[s * 10 + q];
            acc.x += v.x; acc.y += v.y; acc.z += v.z; acc.w += v.w;
        }
        j += 3;
    }
    int rem = end - j;
    if (act && g < rem) {
        int s = col[j + g];
        float4 v = Y4[s * 10 + q];
        acc.x += v.x; acc.y += v.y; acc.z += v.z; acc.w += v.w;
    }

    acc.x += __shfl_sync(0xffffffffu, acc.x, lane + 10) + __shfl_sync(0xffffffffu, acc.x, lane + 20);
    acc.y += __shfl_sync(0xffffffffu, acc.y, lane + 10) + __shfl_sync(0xffffffffu, acc.y, lane + 20);
    acc.z += __shfl_sync(0xffffffffu, acc.z, lane + 10) + __shfl_sync(0xffffffffu, acc.z, lane + 20);
    acc.w += __shfl_sync(0xffffffffu, acc.w, lane + 10) + __shfl_sync(0xffffffffu, acc.w, lane + 20);

    bool own = (lane < 10);
    if (own) {
        acc.x += b2[lane * 4 + 0];
        acc.y += b2[lane * 4 + 1];
        acc.z += b2[lane * 4 + 2];
        acc.w += b2[lane * 4 + 3];
    }
    float m = own ? fmaxf(fmaxf(acc.x, acc.y), fmaxf(acc.z, acc.w)) : -1e30f;
#pragma unroll
    for (int off = 16; off; off >>= 1)
        m = fmaxf(m, __shfl_xor_sync(0xffffffffu, m, off));
    float e0 = __expf(acc.x - m);
    float e1 = __expf(acc.y - m);
    float e2 = __expf(acc.z - m);
    float e3 = __expf(acc.w - m);
    float s = own ? (e0 + e1) + (e2 + e3) : 0.f;
#pragma unroll
    for (int off = 16; off; off >>= 1)
        s += __shfl_xor_sync(0xffffffffu, s, off);
    float inv = 1.f / s;
    if (own) {
        float* o = out + w * C + lane * 4;
        o[0] = e0 * inv;
        o[1] = e1 * inv;
        o[2] = e2 * inv;
        o[3] = e3 * inv;
    }
}

// ---------------- launch ----------------
extern "C" void kernel_launch(void* const* d_in, const int* in_sizes, int n_in,
                              void* d_out, int out_size) {
    const float* h   = (const float*)d_in[0];
    const int*   adj = (const int*)d_in[1];
    const float* W1  = (const float*)d_in[2];
    const float* b1  = (const float*)d_in[3];
    const float* W2  = (const float*)d_in[4];
    const float* b2  = (const float*)d_in[5];
    float* out = (float*)d_out;

    int n = in_sizes[0] / D;
    int e = in_sizes[1] / 2;
    if (n > MAXN) n = MAXN;
    if (e > MAXE) e = MAXE;

    cudaFuncSetAttribute(k_gemm, cudaFuncAttributeMaxDynamicSharedMemorySize, SM_BYTES);

    k_prep<<<(n + 255) / 256, 256>>>(W1, W2, n);
    k_build<<<(e + 255) / 256, 256>>>((const int2*)adj, e);

    k_agg1<<<(n * 16 + 255) / 256, 256>>>(h, n);
    k_gemm<<<(n + 63) / 64, 256, SM_BYTES>>>(b1, n);
    k_agg2_softmax<<<(n * 32 + 255) / 256, 256>>>(b2, out, n);
}